// round 4
// baseline (speedup 1.0000x reference)
#include <cuda_runtime.h>

#define B  512
#define NN 64
#define NE 1024
#define DD 128
#define BN (B*NN)      // 32768
#define BE (B*NE)      // 524288

// ---------------- scratch (device globals; no allocation) ----------------
__device__ __align__(16) float g_s0buf[BN*DD];
__device__ __align__(16) float g_s1buf[BN*DD];
__device__ __align__(16) float g_p[BN*DD];
__device__ float g_rs[BN];
__device__ __align__(16) float g_R[DD*DD];        // W_link^T  : [k][o]
__device__ __align__(16) float g_WrT[2*DD*DD];    // W_r^T     : [k][o], k in [0,256)
__device__ __align__(16) float g_WzT[2*DD*DD];
__device__ __align__(16) float g_WhT[2*DD*DD];
__device__ __align__(16) float g_WoT[DD*DD];
__device__ __align__(16) float g_Wa1T[DD*DD];
__device__ __align__(16) float g_P[2][DD*DD];     // powers of R
__device__ __align__(16) float g_cc[2][DD];       // composed bias
__device__ float g_respart[B*16*DD];              // per-(b, e-chunk) colsums of e0
__device__ float g_resid[B*DD];
__device__ float g_attl[BN];

// ---------------- weight prep: transposes ----------------
__global__ void __launch_bounds__(256) prep_weights(
    const float* __restrict__ Wl, const float* __restrict__ bl,
    const float* __restrict__ Wr, const float* __restrict__ Wz,
    const float* __restrict__ Wh, const float* __restrict__ Wo,
    const float* __restrict__ Wa1)
{
    int idx = blockIdx.x*256 + threadIdx.x;   // 0..32767
    int k = idx >> 7, o = idx & 127;
    g_WrT[idx] = Wr[o*256 + k];
    g_WzT[idx] = Wz[o*256 + k];
    g_WhT[idx] = Wh[o*256 + k];
    if (idx < DD*DD) {
        float v = Wl[o*DD + k];
        g_R[idx] = v;
        g_P[0][idx] = v;
        g_WoT[idx]  = Wo[o*DD + k];
        g_Wa1T[idx] = Wa1[o*DD + k];
    }
    if (idx < DD) g_cc[0][idx] = bl[idx];
}

// P_{t+1} = P_t @ R ; c_{t+1} = c_t @ R + b    (4 applications -> R^5, c5)
__global__ void __launch_bounds__(128) compose_step(int s, const float* __restrict__ bl)
{
    __shared__ float row[DD];
    __shared__ float crow[DD];
    int src = s & 1, dst = src ^ 1;
    int i = blockIdx.x, o = threadIdx.x;
    row[o]  = g_P[src][i*DD + o];
    crow[o] = (i == 0) ? g_cc[src][o] : 0.f;
    __syncthreads();
    float acc = 0.f, cacc = 0.f;
    #pragma unroll 8
    for (int m = 0; m < DD; m++) {
        float rv = g_R[m*DD + o];
        acc  += row[m]  * rv;
        cacc += crow[m] * rv;
    }
    g_P[dst][i*DD + o] = acc;
    if (i == 0) g_cc[dst][o] = cacc + bl[o];
}

__global__ void __launch_bounds__(256) copy_p(const float* __restrict__ p0)
{
    int i = blockIdx.x*256 + threadIdx.x;
    g_p[i] = p0[i];
}

// ---------------- s0 = A @ e0 (per batch), + rowsum(A) ----------------
__global__ void __launch_bounds__(256) k_s0(const float* __restrict__ A,
                                            const float* __restrict__ E0)
{
    __shared__ float sA[64][37];
    __shared__ __align__(16) float sE[32][68];
    const int b = blockIdx.x, c0 = blockIdx.y*64;
    const int tid = threadIdx.x;
    const int tx = tid & 15, ty = tid >> 4;
    const float* Ab = A  + b*NN*NE;
    const float* Eb = E0 + b*NE*DD;
    float acc[4][4] = {};
    float rsum = 0.f;

    for (int k0 = 0; k0 < NE; k0 += 32) {
        #pragma unroll
        for (int i = 0; i < 8; i++) {
            int e = tid + i*256; int r = e >> 5, kk = e & 31;
            sA[r][kk] = Ab[r*NE + k0 + kk];
        }
        #pragma unroll
        for (int i = 0; i < 8; i++) {
            int e = tid + i*256; int kk = e >> 6, c = e & 63;
            sE[kk][c] = Eb[(k0+kk)*DD + c0 + c];
        }
        __syncthreads();
        if (blockIdx.y == 0 && tid < 64) {
            #pragma unroll
            for (int kk = 0; kk < 32; kk++) rsum += sA[tid][kk];
        }
        #pragma unroll
        for (int kk = 0; kk < 32; kk++) {
            float4 wv = *(const float4*)&sE[kk][tx*4];
            #pragma unroll
            for (int j = 0; j < 4; j++) {
                float av = sA[ty + 16*j][kk];
                acc[j][0] += av*wv.x; acc[j][1] += av*wv.y;
                acc[j][2] += av*wv.z; acc[j][3] += av*wv.w;
            }
        }
        __syncthreads();
    }
    #pragma unroll
    for (int j = 0; j < 4; j++) {
        int r = ty + 16*j;
        *(float4*)&g_s0buf[(b*NN + r)*DD + c0 + tx*4] =
            make_float4(acc[j][0], acc[j][1], acc[j][2], acc[j][3]);
    }
    if (blockIdx.y == 0 && tid < 64) g_rs[b*NN + tid] = rsum;
}

// ---------------- e5 = e0 @ R^5 + c5 ; partial colsums for residual ----------------
__global__ void __launch_bounds__(256) k_e5(const float* __restrict__ E0,
                                            float* __restrict__ outE)
{
    __shared__ __align__(16) float sX[64][132];
    __shared__ __align__(16) float sW[16][132];
    const int b = blockIdx.x, r0g = blockIdx.y*64;
    const int tid = threadIdx.x;
    const int tx = tid & 31, ty = tid >> 5;
    const int col = tx*4;
    const float* Eb = E0 + (b*NE + r0g)*DD;

    #pragma unroll
    for (int i = 0; i < 32; i++) {
        int e = tid + i*256; int r = e >> 7, c = e & 127;
        sX[r][c] = Eb[r*DD + c];
    }
    __syncthreads();

    float acc[8][4] = {};
    for (int k0 = 0; k0 < DD; k0 += 16) {
        #pragma unroll
        for (int i = 0; i < 8; i++) {
            int e = tid + i*256; int kk = e >> 7, o = e & 127;
            sW[kk][o] = g_P[0][(k0+kk)*DD + o];
        }
        __syncthreads();
        #pragma unroll
        for (int kk = 0; kk < 16; kk++) {
            float4 wv = *(const float4*)&sW[kk][col];
            #pragma unroll
            for (int j = 0; j < 8; j++) {
                float xv = sX[ty + 8*j][k0+kk];
                acc[j][0] += xv*wv.x; acc[j][1] += xv*wv.y;
                acc[j][2] += xv*wv.z; acc[j][3] += xv*wv.w;
            }
        }
        __syncthreads();
    }
    float c5a = g_cc[0][col+0], c5b = g_cc[0][col+1],
          c5c = g_cc[0][col+2], c5d = g_cc[0][col+3];
    #pragma unroll
    for (int j = 0; j < 8; j++) {
        int r = ty + 8*j;
        *(float4*)&outE[(b*NE + r0g + r)*DD + col] =
            make_float4(acc[j][0]+c5a, acc[j][1]+c5b, acc[j][2]+c5c, acc[j][3]+c5d);
    }
    // residual: colsum of this 64-row e0 tile (deterministic partials, no atomics)
    if (tid < 128) {
        float s = 0.f;
        #pragma unroll
        for (int r = 0; r < 64; r++) s += sX[r][tid];
        g_respart[(b*16 + blockIdx.y)*DD + tid] = s;
    }
}

// residual = sum_n p0 + sum over 16 edge partials   (divide later)
__global__ void __launch_bounds__(128) k_residual(const float* __restrict__ p0)
{
    int b = blockIdx.x, d = threadIdx.x;
    float s = 0.f;
    #pragma unroll
    for (int c = 0; c < 16; c++) s += g_respart[(b*16 + c)*DD + d];
    for (int n = 0; n < NN; n++)  s += p0[(b*NN + n)*DD + d];
    g_resid[b*DD + d] = s;
}

// ---------------- fused GRU step helpers ----------------
__device__ __forceinline__ void gemm256(const float* __restrict__ WT,
    const float (*sL)[132], const float (*sH)[132], float (*sWb)[132],
    int r0, int r1, int col, int tid, float a0[4], float a1[4])
{
    #pragma unroll
    for (int half = 0; half < 2; half++) {
        const float (*src)[132] = half ? sH : sL;
        for (int k0 = 0; k0 < 128; k0 += 32) {
            #pragma unroll
            for (int i = 0; i < 16; i++) {
                int e = tid + i*256; int kk = e >> 7, o = e & 127;
                sWb[kk][o] = WT[(half*128 + k0 + kk)*DD + o];
            }
            __syncthreads();
            #pragma unroll
            for (int kk = 0; kk < 32; kk++) {
                float4 wv = *(const float4*)&sWb[kk][col];
                float x0 = src[r0][k0+kk], x1 = src[r1][k0+kk];
                a0[0]+=x0*wv.x; a0[1]+=x0*wv.y; a0[2]+=x0*wv.z; a0[3]+=x0*wv.w;
                a1[0]+=x1*wv.x; a1[1]+=x1*wv.y; a1[2]+=x1*wv.z; a1[3]+=x1*wv.w;
            }
            __syncthreads();
        }
    }
}

__device__ __forceinline__ void gemm128(const float* __restrict__ WT,
    const float (*src)[132], float (*sWb)[132],
    int r0, int r1, int col, int tid, float a0[4], float a1[4])
{
    for (int k0 = 0; k0 < 128; k0 += 32) {
        #pragma unroll
        for (int i = 0; i < 16; i++) {
            int e = tid + i*256; int kk = e >> 7, o = e & 127;
            sWb[kk][o] = WT[(k0 + kk)*DD + o];
        }
        __syncthreads();
        #pragma unroll
        for (int kk = 0; kk < 32; kk++) {
            float4 wv = *(const float4*)&sWb[kk][col];
            float x0 = src[r0][k0+kk], x1 = src[r1][k0+kk];
            a0[0]+=x0*wv.x; a0[1]+=x0*wv.y; a0[2]+=x0*wv.z; a0[3]+=x0*wv.w;
            a1[0]+=x1*wv.x; a1[1]+=x1*wv.y; a1[2]+=x1*wv.z; a1[3]+=x1*wv.w;
        }
        __syncthreads();
    }
}

// one propagation step: a = s@R + rs*b_link ; r,z,h ; p update. s_out = a.
__global__ void __launch_bounds__(256) gru_step(int flip,
    const float* __restrict__ br, const float* __restrict__ bz,
    const float* __restrict__ bh, const float* __restrict__ bl)
{
    __shared__ __align__(16) float sXX[16][132];  // s_in, later r*p
    __shared__ __align__(16) float sAA[16][132];  // a
    __shared__ __align__(16) float sPP[16][132];  // p
    __shared__ __align__(16) float sW[32][132];
    const float* s_in  = flip ? g_s1buf : g_s0buf;
    float*       s_out = flip ? g_s0buf : g_s1buf;
    const int rb  = blockIdx.x * 16;
    const int tid = threadIdx.x;
    const int tx  = tid & 31, ty = tid >> 5;
    const int r0  = ty*2, r1 = r0 + 1;
    const int col = tx*4;

    #pragma unroll
    for (int i = 0; i < 8; i++) {
        int e = tid + i*256; int r = e >> 7, c = e & 127;
        sXX[r][c] = s_in[(rb+r)*DD + c];
        sPP[r][c] = g_p[(rb+r)*DD + c];
    }
    __syncthreads();
    const float rs0 = g_rs[rb+r0], rs1 = g_rs[rb+r1];

    // phase 1: a = s @ R + rs*b_link
    float A0[4] = {}, A1[4] = {};
    gemm128(g_R, sXX, sW, r0, r1, col, tid, A0, A1);
    #pragma unroll
    for (int q = 0; q < 4; q++) {
        float blv = bl[col+q];
        A0[q] += rs0*blv; A1[q] += rs1*blv;
        sAA[r0][col+q] = A0[q];
        sAA[r1][col+q] = A1[q];
    }
    *(float4*)&s_out[(rb+r0)*DD + col] = make_float4(A0[0],A0[1],A0[2],A0[3]);
    *(float4*)&s_out[(rb+r1)*DD + col] = make_float4(A1[0],A1[1],A1[2],A1[3]);
    __syncthreads();

    // phase 2: r gate, stash r*p into sXX
    float R0[4] = {}, R1[4] = {};
    gemm256(g_WrT, sAA, sPP, sW, r0, r1, col, tid, R0, R1);
    #pragma unroll
    for (int q = 0; q < 4; q++) {
        float b_ = br[col+q];
        float rv0 = 1.f/(1.f + __expf(-(R0[q]+b_)));
        float rv1 = 1.f/(1.f + __expf(-(R1[q]+b_)));
        sXX[r0][col+q] = rv0 * sPP[r0][col+q];
        sXX[r1][col+q] = rv1 * sPP[r1][col+q];
    }
    __syncthreads();

    // phase 3: z gate (kept in regs)
    float Z0[4] = {}, Z1[4] = {};
    gemm256(g_WzT, sAA, sPP, sW, r0, r1, col, tid, Z0, Z1);

    // phase 4: h_hat from [a, r*p], then p update
    float H0[4] = {}, H1[4] = {};
    gemm256(g_WhT, sAA, sXX, sW, r0, r1, col, tid, H0, H1);

    float P0[4], P1[4];
    #pragma unroll
    for (int q = 0; q < 4; q++) {
        float bz_ = bz[col+q], bh_ = bh[col+q];
        float z0 = 1.f/(1.f + __expf(-(Z0[q]+bz_)));
        float z1 = 1.f/(1.f + __expf(-(Z1[q]+bz_)));
        float h0 = tanhf(H0[q] + bh_);
        float h1 = tanhf(H1[q] + bh_);
        float p0v = sPP[r0][col+q], p1v = sPP[r1][col+q];
        P0[q] = (1.f - z0)*p0v + z0*h0;
        P1[q] = (1.f - z1)*p1v + z1*h1;
    }
    *(float4*)&g_p[(rb+r0)*DD + col] = make_float4(P0[0],P0[1],P0[2],P0[3]);
    *(float4*)&g_p[(rb+r1)*DD + col] = make_float4(P1[0],P1[1],P1[2],P1[3]);
}

// ---------------- epilogue: out = tanh(p@WoT+bo), attention logits ----------------
__global__ void __launch_bounds__(256) k_att(
    const float* __restrict__ bo, const float* __restrict__ ba1,
    const float* __restrict__ Wa2, const float* __restrict__ ba2,
    float* __restrict__ outO)
{
    __shared__ __align__(16) float sPP[16][132];
    __shared__ __align__(16) float sA1[16][132];
    __shared__ __align__(16) float sW[32][132];
    const int rb  = blockIdx.x * 16;
    const int tid = threadIdx.x;
    const int tx  = tid & 31, ty = tid >> 5;
    const int r0  = ty*2, r1 = r0 + 1;
    const int col = tx*4;

    #pragma unroll
    for (int i = 0; i < 8; i++) {
        int e = tid + i*256; int r = e >> 7, c = e & 127;
        sPP[r][c] = g_p[(rb+r)*DD + c];
    }
    __syncthreads();

    float O0[4] = {}, O1[4] = {};
    gemm128(g_WoT, sPP, sW, r0, r1, col, tid, O0, O1);
    #pragma unroll
    for (int q = 0; q < 4; q++) {
        float b_ = bo[col+q];
        O0[q] = tanhf(O0[q] + b_);
        O1[q] = tanhf(O1[q] + b_);
    }
    *(float4*)&outO[(rb+r0)*DD + col] = make_float4(O0[0],O0[1],O0[2],O0[3]);
    *(float4*)&outO[(rb+r1)*DD + col] = make_float4(O1[0],O1[1],O1[2],O1[3]);

    float T0[4] = {}, T1[4] = {};
    gemm128(g_Wa1T, sPP, sW, r0, r1, col, tid, T0, T1);
    #pragma unroll
    for (int q = 0; q < 4; q++) {
        float b_ = ba1[col+q];
        sA1[r0][col+q] = tanhf(T0[q] + b_);
        sA1[r1][col+q] = tanhf(T1[q] + b_);
    }
    __syncthreads();

    float d0 = 0.f, d1 = 0.f;
    for (int k = tx; k < 128; k += 32) {
        float w = Wa2[k];
        d0 += sA1[r0][k]*w;
        d1 += sA1[r1][k]*w;
    }
    #pragma unroll
    for (int off = 16; off; off >>= 1) {
        d0 += __shfl_xor_sync(0xFFFFFFFFu, d0, off);
        d1 += __shfl_xor_sync(0xFFFFFFFFu, d1, off);
    }
    if (tx == 0) {
        float bb = ba2[0];
        g_attl[rb+r0] = d0 + bb;
        g_attl[rb+r1] = d1 + bb;
    }
}

// softmax over nodes, weighted sum, residual, relu
__global__ void __launch_bounds__(128) k_final(const float* __restrict__ outO,
                                               float* __restrict__ res)
{
    __shared__ float sl[64];
    __shared__ float se[64];
    const int b = blockIdx.x, tid = threadIdx.x;
    if (tid < 64) sl[tid] = g_attl[b*NN + tid];
    __syncthreads();
    float mx = -1e30f;
    #pragma unroll
    for (int n = 0; n < 64; n++) mx = fmaxf(mx, sl[n]);
    if (tid < 64) se[tid] = __expf(sl[tid] - mx);
    __syncthreads();
    float sum = 0.f;
    #pragma unroll
    for (int n = 0; n < 64; n++) sum += se[n];
    const float* ob = outO + (b*NN)*DD + tid;
    float ws = 0.f;
    #pragma unroll 8
    for (int n = 0; n < 64; n++) ws += se[n]*ob[n*DD];
    float g  = tanhf(ws / sum);
    float rr = g + g_resid[b*DD + tid] * (1.f/1088.f);
    res[b*DD + tid] = fmaxf(rr, 0.f);
}

// ---------------- launch ----------------
extern "C" void kernel_launch(void* const* d_in, const int* in_sizes, int n_in,
                              void* d_out, int out_size)
{
    const float* in_prop = (const float*)d_in[0];
    const float* in_edge = (const float*)d_in[1];
    const float* in_A    = (const float*)d_in[2];
    const float* Wl  = (const float*)d_in[3];
    const float* bl  = (const float*)d_in[4];
    const float* Wr  = (const float*)d_in[5];
    const float* br  = (const float*)d_in[6];
    const float* Wz  = (const float*)d_in[7];
    const float* bz  = (const float*)d_in[8];
    const float* Wh  = (const float*)d_in[9];
    const float* bh  = (const float*)d_in[10];
    const float* Wa1 = (const float*)d_in[11];
    const float* ba1 = (const float*)d_in[12];
    const float* Wa2 = (const float*)d_in[13];
    const float* ba2 = (const float*)d_in[14];
    const float* Wo  = (const float*)d_in[15];
    const float* bo  = (const float*)d_in[16];

    float* out  = (float*)d_out;
    float* res  = out;                       // [512,128]
    float* outO = out + B*DD;                // [512,64,128]
    float* outE = out + B*DD + BN*DD;        // [512,1024,128]

    copy_p<<<BN*DD/256, 256>>>(in_prop);
    prep_weights<<<128, 256>>>(Wl, bl, Wr, Wz, Wh, Wo, Wa1);
    for (int s = 0; s < 4; s++) compose_step<<<128, 128>>>(s, bl);

    k_s0<<<dim3(B, 2), 256>>>(in_A, in_edge);
    k_e5<<<dim3(B, 16), 256>>>(in_edge, outE);
    k_residual<<<B, 128>>>(in_prop);

    for (int t = 0; t < 5; t++)
        gru_step<<<BN/16, 256>>>(t & 1, br, bz, bh, bl);

    k_att<<<BN/16, 256>>>(bo, ba1, Wa2, ba2, outO);
    k_final<<<B, 128>>>(outO, res);
}

// round 6
// speedup vs baseline: 3.0647x; 3.0647x over previous
#include <cuda_runtime.h>
#include <cstdint>

#define B  512
#define NN 64
#define NE 1024
#define DD 128
#define BN (B*NN)      // 32768
#define BE (B*NE)      // 524288
#define LT 132
#define TILE_W (128*LT)   // words per 128x132 tile

// ---------------- scratch (device globals; no allocation) ----------------
__device__ __align__(16) float g_P[2][DD*DD];   // powers of W_link, row-major [o][k]
__device__ __align__(16) float g_c5[DD];
__device__ __align__(16) float g_s0buf[BN*DD];
__device__ __align__(16) float g_s1buf[BN*DD];
__device__ __align__(16) float g_p[BN*DD];
__device__ float g_rs[BN];
__device__ float g_respart[(BE/128)*DD];
__device__ float g_resid[B*DD];
__device__ float g_attl[BN];

// ---------------- helpers ----------------
__device__ __forceinline__ uint32_t f2tf(float f){
    uint32_t u; asm("cvt.rna.tf32.f32 %0, %1;" : "=r"(u) : "f"(f)); return u;
}
__device__ __forceinline__ float sigf(float x){ return 1.f/(1.f+__expf(-x)); }

__device__ __forceinline__ void mma8(float c[4], const uint32_t a[4], const uint32_t b[2]){
    asm volatile("mma.sync.aligned.m16n8k8.row.col.f32.tf32.tf32.f32 "
        "{%0,%1,%2,%3}, {%4,%5,%6,%7}, {%8,%9}, {%0,%1,%2,%3};"
        : "+f"(c[0]),"+f"(c[1]),"+f"(c[2]),"+f"(c[3])
        : "r"(a[0]),"r"(a[1]),"r"(a[2]),"r"(a[3]),"r"(b[0]),"r"(b[1]));
}

// load 128x128 fp32 (row stride `stride`) -> smem [128][LT] tf32
__device__ __forceinline__ void load_tile(uint32_t* dst, const float* __restrict__ src,
                                          int stride, int tid){
    #pragma unroll
    for(int i=0;i<16;i++){
        int idx = i*256 + tid;
        int r = idx>>5, c4 = (idx&31)<<2;
        float4 v = *(const float4*)(src + (long)r*stride + c4);
        uint32_t* d = dst + r*LT + c4;
        d[0]=f2tf(v.x); d[1]=f2tf(v.y); d[2]=f2tf(v.z); d[3]=f2tf(v.w);
    }
}

// per-warp 64x32 output tile over K=128. A [m][k] ld LT, B [n][k] ld LT.
__device__ __forceinline__ void gemm_slab(const uint32_t* sA, const uint32_t* sB,
                                          int wm, int wn, int lane, float (&acc)[16][4]){
    #pragma unroll
    for(int ks=0; ks<16; ks++){
        const int k0 = ks*8;
        uint32_t a[4][4], b[4][2];
        #pragma unroll
        for(int mi=0;mi<4;mi++){
            const uint32_t* p = sA + (wm+16*mi+(lane>>2))*LT + k0 + (lane&3);
            a[mi][0]=p[0]; a[mi][1]=p[8*LT]; a[mi][2]=p[4]; a[mi][3]=p[8*LT+4];
        }
        #pragma unroll
        for(int ni=0;ni<4;ni++){
            const uint32_t* p = sB + (wn+8*ni+(lane>>2))*LT + k0 + (lane&3);
            b[ni][0]=p[0]; b[ni][1]=p[4];
        }
        #pragma unroll
        for(int mi=0;mi<4;mi++)
            #pragma unroll
            for(int ni=0;ni<4;ni++)
                mma8(acc[mi*4+ni], a[mi], b[ni]);
    }
}

// ---------------- tiny setup kernels ----------------
__global__ void __launch_bounds__(256) copy_p(const float* __restrict__ p0){
    int i = blockIdx.x*256 + threadIdx.x;
    g_p[i] = p0[i];
}

// mode 0: P0 = W@W ; 1: P1 = P0@P0 ; 2: P0 = P1@W   (-> P0 = W^5)
__global__ void __launch_bounds__(1024) k_sqmm(int mode, const float* __restrict__ Wl){
    extern __shared__ float s[];
    float* sY = s;             // [128][128]
    float* sX = s + DD*DD;     // [8][128]
    const float* X = (mode==0)? Wl : (mode==1? g_P[0] : g_P[1]);
    const float* Y = (mode==1)? g_P[0] : Wl;
    float* Z = (mode==1)? g_P[1] : g_P[0];
    int tid = threadIdx.x;
    #pragma unroll
    for(int j=0;j<16;j++) sY[j*1024+tid] = Y[j*1024+tid];
    int r0 = blockIdx.x*8;
    sX[tid] = X[r0*DD + tid];
    __syncthreads();
    int ty = tid>>7, o = tid&127;
    float acc = 0.f;
    #pragma unroll 16
    for(int m=0;m<DD;m++) acc += sX[ty*DD+m]*sY[m*DD+o];
    Z[(r0+ty)*DD + o] = acc;
}

// c5 = sum_{j=0..4} W^j b   via c <- W c + b, 5 times
__global__ void __launch_bounds__(128) k_cvec(const float* __restrict__ Wl,
                                              const float* __restrict__ bl){
    __shared__ float c[DD];
    int o = threadIdx.x;
    c[o] = 0.f; __syncthreads();
    const float4* W4 = (const float4*)(Wl + o*DD);
    for(int t=0;t<5;t++){
        float a = bl[o];
        #pragma unroll 8
        for(int k=0;k<32;k++){
            float4 w = W4[k];
            a += w.x*c[4*k] + w.y*c[4*k+1] + w.z*c[4*k+2] + w.w*c[4*k+3];
        }
        __syncthreads(); c[o] = a; __syncthreads();
    }
    g_c5[o] = c[o];
}

// ---------------- s0 = A @ e0 (per batch) + rowsum(A) ----------------
__global__ void __launch_bounds__(256) k_s0(const float* __restrict__ A,
                                            const float* __restrict__ E0){
    extern __shared__ uint32_t sm[];
    uint32_t* sA = sm;            // [64][68]  (A chunk, [m][k])
    uint32_t* sE = sm + 64*68;    // [64][136] (E chunk, [k][n])
    const int tid=threadIdx.x, lane=tid&31, wid=tid>>5;
    const int wm=(wid>>2)*32, wn=(wid&3)*32;
    const int bb_ = blockIdx.x;
    const float* Ab = A  + (long)bb_*NN*NE;
    const float* Eb = E0 + (long)bb_*NE*DD;
    float acc[8][4] = {};
    float rsum = 0.f;
    for(int kc=0;kc<16;kc++){
        int kb = kc*64;
        #pragma unroll
        for(int i=0;i<4;i++){
            int idx=i*256+tid; int r=idx>>4, c4=(idx&15)<<2;
            float4 v = *(const float4*)(Ab + (long)r*NE + kb + c4);
            uint32_t* d = sA + r*68 + c4;
            d[0]=f2tf(v.x); d[1]=f2tf(v.y); d[2]=f2tf(v.z); d[3]=f2tf(v.w);
        }
        #pragma unroll
        for(int i=0;i<8;i++){
            int idx=i*256+tid; int r=idx>>5, c4=(idx&31)<<2;
            float4 v = *(const float4*)(Eb + (long)(kb+r)*DD + c4);
            uint32_t* d = sE + r*136 + c4;
            d[0]=f2tf(v.x); d[1]=f2tf(v.y); d[2]=f2tf(v.z); d[3]=f2tf(v.w);
        }
        __syncthreads();
        if(tid < 64){
            #pragma unroll 16
            for(int kk=0;kk<64;kk++) rsum += __uint_as_float(sA[tid*68+kk]);
        }
        #pragma unroll
        for(int ks=0;ks<8;ks++){
            int k0=ks*8;
            uint32_t a[2][4], bf[4][2];
            #pragma unroll
            for(int mi=0;mi<2;mi++){
                const uint32_t* p = sA + (wm+16*mi+(lane>>2))*68 + k0 + (lane&3);
                a[mi][0]=p[0]; a[mi][1]=p[8*68]; a[mi][2]=p[4]; a[mi][3]=p[8*68+4];
            }
            #pragma unroll
            for(int ni=0;ni<4;ni++){
                const uint32_t* p = sE + (k0+(lane&3))*136 + wn + 8*ni + (lane>>2);
                bf[ni][0]=p[0]; bf[ni][1]=p[4*136];
            }
            #pragma unroll
            for(int mi=0;mi<2;mi++)
                #pragma unroll
                for(int ni=0;ni<4;ni++)
                    mma8(acc[mi*4+ni], a[mi], bf[ni]);
        }
        __syncthreads();
    }
    #pragma unroll
    for(int mi=0;mi<2;mi++)
    #pragma unroll
    for(int h=0;h<2;h++){
        int row = wm + 16*mi + (lane>>2) + 8*h;
        #pragma unroll
        for(int ni=0;ni<4;ni++){
            int col = wn + 8*ni + (lane&3)*2;
            *(float2*)&g_s0buf[((long)bb_*NN + row)*DD + col] =
                make_float2(acc[mi*4+ni][2*h], acc[mi*4+ni][2*h+1]);
        }
    }
    if(tid < 64) g_rs[bb_*NN + tid] = rsum;
}

// ---------------- e5 = e0 @ (W^5)^T + c5 ; residual colsums ----------------
__global__ void __launch_bounds__(256) k_e5(const float* __restrict__ E0,
                                            float* __restrict__ outE){
    extern __shared__ uint32_t sm[];
    uint32_t* sX = sm; uint32_t* sW = sm + TILE_W;
    const int tid=threadIdx.x, lane=tid&31, wid=tid>>5;
    const int wm=(wid>>2)*64, wn=(wid&3)*32;
    const long rb = (long)blockIdx.x*128;
    load_tile(sX, E0 + rb*DD, DD, tid);
    load_tile(sW, &g_P[0][0], DD, tid);
    __syncthreads();
    float acc[16][4] = {};
    gemm_slab(sX, sW, wm, wn, lane, acc);
    #pragma unroll
    for(int mi=0;mi<4;mi++)
    #pragma unroll
    for(int h=0;h<2;h++){
        long grow = rb + wm + 16*mi + (lane>>2) + 8*h;
        #pragma unroll
        for(int ni=0;ni<4;ni++){
            int col = wn + 8*ni + (lane&3)*2;
            *(float2*)&outE[grow*DD + col] =
                make_float2(acc[mi*4+ni][2*h] + g_c5[col],
                            acc[mi*4+ni][2*h+1] + g_c5[col+1]);
        }
    }
    if(tid < DD){
        float s = 0.f;
        #pragma unroll 16
        for(int r=0;r<128;r++) s += __uint_as_float(sX[r*LT+tid]);
        g_respart[blockIdx.x*DD + tid] = s;
    }
}

__global__ void __launch_bounds__(128) k_residual(const float* __restrict__ p0){
    int bb_ = blockIdx.x, d = threadIdx.x;
    float s = 0.f;
    #pragma unroll
    for(int c = 0; c < 8; c++) s += g_respart[(bb_*8 + c)*DD + d];
    for(int n = 0; n < NN; n++) s += p0[((long)bb_*NN + n)*DD + d];
    g_resid[bb_*DD + d] = s;
}

// ---------------- fused GRU step ----------------
__global__ void __launch_bounds__(256) k_gru(int flip,
    const float* __restrict__ Wl, const float* __restrict__ bl,
    const float* __restrict__ Wr, const float* __restrict__ br,
    const float* __restrict__ Wz, const float* __restrict__ bz,
    const float* __restrict__ Wh, const float* __restrict__ bh)
{
    extern __shared__ uint32_t sm[];
    uint32_t* T1 = sm;                 // s -> a
    uint32_t* Tp = sm + TILE_W;        // p -> r*p
    uint32_t* WB = sm + 2*TILE_W;      // staged weight slab
    const float* s_in  = flip ? g_s1buf : g_s0buf;
    float*       s_out = flip ? g_s0buf : g_s1buf;
    const int tid=threadIdx.x, lane=tid&31, wid=tid>>5;
    const int wm=(wid>>2)*64, wn=(wid&3)*32;
    const long rb = (long)blockIdx.x*128;

    load_tile(T1, s_in + rb*DD, DD, tid);
    load_tile(Tp, g_p  + rb*DD, DD, tid);
    load_tile(WB, Wl, DD, tid);
    __syncthreads();
    float acc[16][4] = {};
    gemm_slab(T1, WB, wm, wn, lane, acc);
    __syncthreads();
    // a = s@Wl^T + rs*bl  -> s_out (fp32) and T1 (tf32)
    #pragma unroll
    for(int mi=0;mi<4;mi++)
    #pragma unroll
    for(int h=0;h<2;h++){
        int rl = wm+16*mi+(lane>>2)+8*h;
        long grow = rb + rl;
        float rsv = g_rs[grow];
        #pragma unroll
        for(int ni=0;ni<4;ni++){
            int col = wn+8*ni+(lane&3)*2;
            float v0 = acc[mi*4+ni][2*h]   + rsv*bl[col];
            float v1 = acc[mi*4+ni][2*h+1] + rsv*bl[col+1];
            *(float2*)&s_out[grow*DD+col] = make_float2(v0,v1);
            T1[rl*LT+col]   = f2tf(v0);
            T1[rl*LT+col+1] = f2tf(v1);
        }
    }
    // ---- z gate: a@Wz_a + p@Wz_p ----
    load_tile(WB, Wz, 2*DD, tid);
    __syncthreads();
    #pragma unroll
    for(int f=0;f<16;f++){acc[f][0]=acc[f][1]=acc[f][2]=acc[f][3]=0.f;}
    gemm_slab(T1, WB, wm, wn, lane, acc);
    __syncthreads();
    load_tile(WB, Wz + DD, 2*DD, tid);
    __syncthreads();
    gemm_slab(Tp, WB, wm, wn, lane, acc);
    float zr[16][4];
    #pragma unroll
    for(int mi=0;mi<4;mi++)
    #pragma unroll
    for(int h=0;h<2;h++)
    #pragma unroll
    for(int ni=0;ni<4;ni++){
        int col = wn+8*ni+(lane&3)*2;
        zr[mi*4+ni][2*h]   = sigf(acc[mi*4+ni][2*h]   + bz[col]);
        zr[mi*4+ni][2*h+1] = sigf(acc[mi*4+ni][2*h+1] + bz[col+1]);
    }
    // ---- r gate: a@Wr_a + p@Wr_p ; then Tp <- tf32(r*p) ----
    __syncthreads();
    load_tile(WB, Wr, 2*DD, tid);
    __syncthreads();
    #pragma unroll
    for(int f=0;f<16;f++){acc[f][0]=acc[f][1]=acc[f][2]=acc[f][3]=0.f;}
    gemm_slab(T1, WB, wm, wn, lane, acc);
    __syncthreads();
    load_tile(WB, Wr + DD, 2*DD, tid);
    __syncthreads();
    gemm_slab(Tp, WB, wm, wn, lane, acc);
    __syncthreads();   // all reads of Tp complete before overwrite
    #pragma unroll
    for(int mi=0;mi<4;mi++)
    #pragma unroll
    for(int h=0;h<2;h++){
        int rl = wm+16*mi+(lane>>2)+8*h;
        long grow = rb + rl;
        #pragma unroll
        for(int ni=0;ni<4;ni++){
            int col = wn+8*ni+(lane&3)*2;
            float2 pv = *(const float2*)&g_p[grow*DD + col];
            float r0 = sigf(acc[mi*4+ni][2*h]   + br[col]);
            float r1 = sigf(acc[mi*4+ni][2*h+1] + br[col+1]);
            Tp[rl*LT+col]   = f2tf(r0*pv.x);
            Tp[rl*LT+col+1] = f2tf(r1*pv.y);
        }
    }
    load_tile(WB, Wh, 2*DD, tid);
    __syncthreads();
    // ---- h gate: a@Wh_a + (r*p)@Wh_p ; p update ----
    #pragma unroll
    for(int f=0;f<16;f++){acc[f][0]=acc[f][1]=acc[f][2]=acc[f][3]=0.f;}
    gemm_slab(T1, WB, wm, wn, lane, acc);
    __syncthreads();
    load_tile(WB, Wh + DD, 2*DD, tid);
    __syncthreads();
    gemm_slab(Tp, WB, wm, wn, lane, acc);
    #pragma unroll
    for(int mi=0;mi<4;mi++)
    #pragma unroll
    for(int h=0;h<2;h++){
        int rl = wm+16*mi+(lane>>2)+8*h;
        long grow = rb + rl;
        #pragma unroll
        for(int ni=0;ni<4;ni++){
            int col = wn+8*ni+(lane&3)*2;
            float2 pv = *(const float2*)&g_p[grow*DD + col];
            float h0 = tanhf(acc[mi*4+ni][2*h]   + bh[col]);
            float h1 = tanhf(acc[mi*4+ni][2*h+1] + bh[col+1]);
            float z0 = zr[mi*4+ni][2*h], z1 = zr[mi*4+ni][2*h+1];
            *(float2*)&g_p[grow*DD + col] =
                make_float2((1.f-z0)*pv.x + z0*h0, (1.f-z1)*pv.y + z1*h1);
        }
    }
}

// ---------------- epilogue: out = tanh(p@Wo^T+bo), attention logits ----------------
__global__ void __launch_bounds__(256) k_att(
    const float* __restrict__ Wo,  const float* __restrict__ bo,
    const float* __restrict__ Wa1, const float* __restrict__ ba1,
    const float* __restrict__ Wa2, const float* __restrict__ ba2,
    float* __restrict__ outO)
{
    extern __shared__ uint32_t sm[];
    uint32_t* T1 = sm; uint32_t* WB = sm + TILE_W;
    const int tid=threadIdx.x, lane=tid&31, wid=tid>>5;
    const int wm=(wid>>2)*64, wn=(wid&3)*32;
    const long rb = (long)blockIdx.x*128;

    load_tile(T1, g_p + rb*DD, DD, tid);
    load_tile(WB, Wo, DD, tid);
    __syncthreads();
    float acc[16][4] = {};
    gemm_slab(T1, WB, wm, wn, lane, acc);
    #pragma unroll
    for(int mi=0;mi<4;mi++)
    #pragma unroll
    for(int h=0;h<2;h++){
        long grow = rb + wm+16*mi+(lane>>2)+8*h;
        #pragma unroll
        for(int ni=0;ni<4;ni++){
            int col = wn+8*ni+(lane&3)*2;
            *(float2*)&outO[grow*DD + col] =
                make_float2(tanhf(acc[mi*4+ni][2*h]   + bo[col]),
                            tanhf(acc[mi*4+ni][2*h+1] + bo[col+1]));
        }
    }
    __syncthreads();
    load_tile(WB, Wa1, DD, tid);
    __syncthreads();
    #pragma unroll
    for(int f=0;f<16;f++){acc[f][0]=acc[f][1]=acc[f][2]=acc[f][3]=0.f;}
    gemm_slab(T1, WB, wm, wn, lane, acc);
    __syncthreads();   // T1 reads done; reuse as fp32 tanh storage
    float* sT = (float*)T1;
    #pragma unroll
    for(int mi=0;mi<4;mi++)
    #pragma unroll
    for(int h=0;h<2;h++){
        int rl = wm+16*mi+(lane>>2)+8*h;
        #pragma unroll
        for(int ni=0;ni<4;ni++){
            int col = wn+8*ni+(lane&3)*2;
            sT[rl*LT+col]   = tanhf(acc[mi*4+ni][2*h]   + ba1[col]);
            sT[rl*LT+col+1] = tanhf(acc[mi*4+ni][2*h+1] + ba1[col+1]);
        }
    }
    __syncthreads();
    if(tid < 128){
        float d = 0.f;
        #pragma unroll 16
        for(int c=0;c<DD;c++) d += sT[tid*LT+c]*Wa2[c];
        g_attl[rb + tid] = d + ba2[0];
    }
}

// softmax over nodes, weighted sum, residual, relu
__global__ void __launch_bounds__(128) k_final(const float* __restrict__ outO,
                                               float* __restrict__ res)
{
    __shared__ float sl[64];
    __shared__ float se[64];
    const int bb_ = blockIdx.x, tid = threadIdx.x;
    if (tid < 64) sl[tid] = g_attl[bb_*NN + tid];
    __syncthreads();
    float mx = -1e30f;
    #pragma unroll
    for (int n = 0; n < 64; n++) mx = fmaxf(mx, sl[n]);
    if (tid < 64) se[tid] = __expf(sl[tid] - mx);
    __syncthreads();
    float sum = 0.f;
    #pragma unroll
    for (int n = 0; n < 64; n++) sum += se[n];
    const float* ob = outO + (long)bb_*NN*DD + tid;
    float ws = 0.f;
    #pragma unroll 8
    for (int n = 0; n < 64; n++) ws += se[n]*ob[n*DD];
    float g  = tanhf(ws / sum);
    float rr = g + g_resid[bb_*DD + tid] * (1.f/1088.f);
    res[bb_*DD + tid] = fmaxf(rr, 0.f);
}

// ---------------- launch ----------------
extern "C" void kernel_launch(void* const* d_in, const int* in_sizes, int n_in,
                              void* d_out, int out_size)
{
    const float* in_prop = (const float*)d_in[0];
    const float* in_edge = (const float*)d_in[1];
    const float* in_A    = (const float*)d_in[2];
    const float* Wl  = (const float*)d_in[3];
    const float* bl  = (const float*)d_in[4];
    const float* Wr  = (const float*)d_in[5];
    const float* br  = (const float*)d_in[6];
    const float* Wz  = (const float*)d_in[7];
    const float* bz  = (const float*)d_in[8];
    const float* Wh  = (const float*)d_in[9];
    const float* bh  = (const float*)d_in[10];
    const float* Wa1 = (const float*)d_in[11];
    const float* ba1 = (const float*)d_in[12];
    const float* Wa2 = (const float*)d_in[13];
    const float* ba2 = (const float*)d_in[14];
    const float* Wo  = (const float*)d_in[15];
    const float* bo  = (const float*)d_in[16];

    float* out  = (float*)d_out;
    float* res  = out;                       // [512,128]
    float* outO = out + B*DD;                // [512,64,128]
    float* outE = out + B*DD + BN*DD;        // [512,1024,128]

    cudaFuncSetAttribute(k_sqmm, cudaFuncAttributeMaxDynamicSharedMemorySize, (DD*DD+8*DD)*4);
    cudaFuncSetAttribute(k_s0,   cudaFuncAttributeMaxDynamicSharedMemorySize, (64*68+64*136)*4);
    cudaFuncSetAttribute(k_e5,   cudaFuncAttributeMaxDynamicSharedMemorySize, 2*TILE_W*4);
    cudaFuncSetAttribute(k_gru,  cudaFuncAttributeMaxDynamicSharedMemorySize, 3*TILE_W*4);
    cudaFuncSetAttribute(k_att,  cudaFuncAttributeMaxDynamicSharedMemorySize, 2*TILE_W*4);

    copy_p<<<BN*DD/256, 256>>>(in_prop);
    k_sqmm<<<16, 1024, (DD*DD+8*DD)*4>>>(0, Wl);
    k_sqmm<<<16, 1024, (DD*DD+8*DD)*4>>>(1, Wl);
    k_sqmm<<<16, 1024, (DD*DD+8*DD)*4>>>(2, Wl);
    k_cvec<<<1, 128>>>(Wl, bl);

    k_s0<<<B, 256, (64*68+64*136)*4>>>(in_A, in_edge);
    k_e5<<<BE/128, 256, 2*TILE_W*4>>>(in_edge, outE);
    k_residual<<<B, 128>>>(in_prop);

    for (int t = 0; t < 5; t++)
        k_gru<<<BN/128, 256, 3*TILE_W*4>>>(t & 1, Wl, bl, Wr, br, Wz, bz, Wh, bh);

    k_att<<<BN/128, 256, 2*TILE_W*4>>>(Wo, bo, Wa1, ba1, Wa2, ba2, outO);
    k_final<<<B, 128>>>(outO, res);
}